// round 16
// baseline (speedup 1.0000x reference)
#include <cuda_runtime.h>
#include <cuda_fp16.h>
#include <math.h>
#include <stdint.h>

#define T_TOK 8192
#define DIM   2048
#define NE    8
#define RK    16
#define ER    128

// ---------------- device scratch ----------------
__device__ int   g_idx[T_TOK];
__device__ float g_w[T_TOK];
__device__ __align__(256) __half g_xh[T_TOK * DIM];
__device__ __align__(256) __half g_wh[DIM * DIM];
__device__ __align__(256) __half g_lAt[ER * DIM];   // [n=e*16+r][k]
__device__ __align__(256) __half g_lBt[DIM * ER];   // [n][k2]
__device__ __align__(256) __half g_hm[T_TOK * ER];  // masked scaled h

__device__ __forceinline__ float gelu_exact(float v) {
    return 0.5f * v * (1.0f + erff(v * 0.7071067811865476f));
}
__device__ __forceinline__ uint32_t smem_u32(const void* p) {
    uint32_t a;
    asm("{ .reg .u64 t; cvta.to.shared.u64 t, %1; cvt.u32.u64 %0, t; }" : "=r"(a) : "l"(p));
    return a;
}
#define CP_ASYNC16(dst, src) asm volatile("cp.async.cg.shared.global [%0], [%1], 16;" :: "r"(dst), "l"(src))
#define CP_COMMIT()          asm volatile("cp.async.commit_group;" ::: "memory")
#define CP_WAIT(n)           asm volatile("cp.async.wait_group %0;" :: "n"(n) : "memory")

__device__ __forceinline__ void ldsm4(uint32_t* r, uint32_t addr) {
    asm volatile("ldmatrix.sync.aligned.m8n8.x4.shared.b16 {%0,%1,%2,%3}, [%4];"
        : "=r"(r[0]), "=r"(r[1]), "=r"(r[2]), "=r"(r[3]) : "r"(addr));
}
__device__ __forceinline__ void mma16816(float* d, const uint32_t* a, const uint32_t* b) {
    asm volatile("mma.sync.aligned.m16n8k16.row.col.f32.f16.f16.f32 "
        "{%0,%1,%2,%3}, {%4,%5,%6,%7}, {%8,%9}, {%0,%1,%2,%3};"
        : "+f"(d[0]), "+f"(d[1]), "+f"(d[2]), "+f"(d[3])
        : "r"(a[0]), "r"(a[1]), "r"(a[2]), "r"(a[3]), "r"(b[0]), "r"(b[1]));
}
// smem tile: rows x 64B (32 halves), swizzled
__device__ __forceinline__ uint32_t sw_off(int row, int chunk) {
    return (uint32_t)(row * 64 + ((chunk ^ ((row >> 1) & 3)) << 4));
}

// ---------------- prep: router (2 tok/warp) + pack_lA ----------------
__global__ __launch_bounds__(256) void prep_fused(
    const float* __restrict__ x, const float* __restrict__ gw,
    const float* __restrict__ gb, float* __restrict__ probs,
    const float* __restrict__ lA)
{
    const int b = blockIdx.x;
    if (b < 512) {
        // 16 tokens/block, 2 tokens/warp
        const int warp = threadIdx.x >> 5, lane = threadIdx.x & 31;
        const int tbase = b * 16 + warp * 2;

        float acc[2][NE];
#pragma unroll
        for (int tt = 0; tt < 2; tt++)
#pragma unroll
            for (int e = 0; e < NE; e++) acc[tt][e] = 0.f;

#pragma unroll 1
        for (int i = 0; i < 16; i++) {
            int k = lane * 4 + i * 128;
            float4 v[2];
#pragma unroll
            for (int tt = 0; tt < 2; tt++) {
                v[tt] = *(const float4*)(x + (size_t)(tbase + tt) * DIM + k);
                __half h[4] = {__float2half_rn(v[tt].x), __float2half_rn(v[tt].y),
                               __float2half_rn(v[tt].z), __float2half_rn(v[tt].w)};
                *(uint2*)(g_xh + (size_t)(tbase + tt) * DIM + k) = *(uint2*)h;
            }
#pragma unroll
            for (int e = 0; e < NE; e++) {
                float4 g = __ldg((const float4*)(gw + e * DIM + k));
#pragma unroll
                for (int tt = 0; tt < 2; tt++)
                    acc[tt][e] += v[tt].x * g.x + v[tt].y * g.y
                                + v[tt].z * g.z + v[tt].w * g.w;
            }
        }
#pragma unroll
        for (int tt = 0; tt < 2; tt++) {
#pragma unroll
            for (int e = 0; e < NE; e++)
#pragma unroll
                for (int o = 16; o > 0; o >>= 1)
                    acc[tt][e] += __shfl_xor_sync(0xffffffffu, acc[tt][e], o);
            if (lane == 0) {
                int t = tbase + tt;
                float m = -1e30f;
#pragma unroll
                for (int e = 0; e < NE; e++) { acc[tt][e] += gb[e]; m = fmaxf(m, acc[tt][e]); }
                float p[NE], s = 0.f;
#pragma unroll
                for (int e = 0; e < NE; e++) { p[e] = __expf(acc[tt][e] - m); s += p[e]; }
                float inv = 1.f / s;
                int best = 0; float bp = -1.f;
#pragma unroll
                for (int e = 0; e < NE; e++) {
                    p[e] *= inv;
                    probs[t * NE + e] = p[e];
                    if (p[e] > bp) { bp = p[e]; best = e; }
                }
                g_idx[t] = best; g_w[t] = bp;
            }
        }
    } else {
        int idx = (b - 512) * 256 + threadIdx.x;
        int k = idx & (DIM - 1), n = idx >> 11;
        g_lAt[idx] = __float2half_rn(lA[(size_t)((n >> 4) * DIM + k) * RK + (n & 15)]);
    }
}

// ---------------- LoRA-A (blocks<128) + conv_w + pack_lB filler blocks ----------------
#define LA_STAGE 12288
#define LA_WOFF  4096
__global__ __launch_bounds__(256, 2) void loraA_fused(
    const float* __restrict__ bw, const float* __restrict__ lB)
{
    const int blk = blockIdx.x;
    if (blk >= 128) {
        if (blk < 2176) {
            // conv_w: 2 float4 per thread
            int i0 = (blk - 128) * 512 + threadIdx.x;
#pragma unroll
            for (int r = 0; r < 2; r++) {
                int i = i0 + r * 256;
                float4 v = ((const float4*)bw)[i];
                __half h[4] = {__float2half_rn(v.x), __float2half_rn(v.y),
                               __float2half_rn(v.z), __float2half_rn(v.w)};
                ((uint2*)g_wh)[i] = *(uint2*)h;
            }
        } else {
            int idx = (blk - 2176) * 256 + threadIdx.x;
            int k2 = idx & 127, n = idx >> 7;
            g_lBt[idx] = __float2half_rn(lB[(size_t)((k2 >> 4) * RK + (k2 & 15)) * DIM + n]);
        }
        return;
    }

    extern __shared__ char sm[];
    uint32_t sb = smem_u32(sm);
    const int tid = threadIdx.x, wid = tid >> 5, lane = tid & 31;
    const int t0 = blk * 64;
    const int warp_m = (wid & 1) * 32, warp_n = (wid >> 1) * 32;

    float acc[2][4][4];
#pragma unroll
    for (int a = 0; a < 2; a++)
#pragma unroll
        for (int b = 0; b < 4; b++)
#pragma unroll
            for (int c = 0; c < 4; c++) acc[a][b][c] = 0.f;

#define LA_ISSUE(s, k0) do {                                                  \
    uint32_t st = sb + (uint32_t)(s) * LA_STAGE;                              \
    { int row = tid >> 2, ch = tid & 3;                                       \
      CP_ASYNC16(st + sw_off(row, ch), g_xh + (size_t)(t0 + row) * DIM + (k0) + ch * 8); } \
    _Pragma("unroll")                                                         \
    for (int i = 0; i < 2; i++) {                                             \
        int idx = tid + i * 256;                                              \
        int row = idx >> 2, ch = idx & 3;                                     \
        CP_ASYNC16(st + LA_WOFF + sw_off(row, ch), g_lAt + (size_t)row * DIM + (k0) + ch * 8); \
    }                                                                         \
    CP_COMMIT();                                                              \
} while (0)

    LA_ISSUE(0, 0);
    LA_ISSUE(1, 32);
    LA_ISSUE(2, 64);
    for (int c = 0; c < 64; c++) {
        if (c < 62) { CP_WAIT(2); } else if (c == 62) { CP_WAIT(1); } else { CP_WAIT(0); }
        __syncthreads();
        if (c + 3 < 64) LA_ISSUE((c + 3) & 3, (c + 3) * 32);
        uint32_t base = sb + (uint32_t)(c & 3) * LA_STAGE;
#pragma unroll
        for (int kk = 0; kk < 2; kk++) {
            uint32_t ah[2][4];
#pragma unroll
            for (int mi = 0; mi < 2; mi++) {
                int r = warp_m + mi * 16 + (lane & 15);
                ldsm4(ah[mi], base + sw_off(r, kk * 2 + (lane >> 4)));
            }
#pragma unroll
            for (int p = 0; p < 2; p++) {
                uint32_t bh[4];
                int r = warp_n + p * 16 + (lane & 7) + ((lane >> 4) << 3);
                ldsm4(bh, base + LA_WOFF + sw_off(r, kk * 2 + ((lane >> 3) & 1)));
#pragma unroll
                for (int mi = 0; mi < 2; mi++) {
                    mma16816(acc[mi][p * 2], ah[mi], bh);
                    mma16816(acc[mi][p * 2 + 1], ah[mi], bh + 2);
                }
            }
        }
    }
#pragma unroll
    for (int mi = 0; mi < 2; mi++) {
#pragma unroll
        for (int h = 0; h < 2; h++) {
            int t = t0 + warp_m + mi * 16 + (lane >> 2) + h * 8;
            int se = g_idx[t];
            float wv = g_w[t];
#pragma unroll
            for (int nt = 0; nt < 4; nt++) {
                int col = warp_n + nt * 8 + (lane & 3) * 2;
                float v0 = ((col >> 4) == se) ? wv * gelu_exact(acc[mi][nt][h * 2]) : 0.f;
                float v1 = (((col + 1) >> 4) == se) ? wv * gelu_exact(acc[mi][nt][h * 2 + 1]) : 0.f;
                __half2 p2 = __floats2half2_rn(v0, v1);
                *(uint32_t*)(g_hm + (size_t)t * ER + col) = *(uint32_t*)&p2;
            }
        }
    }
}

// ---------------- main kernel: BM=BN=128, BK=32, 6 stages, paired chunks ----------------
#define ST_WH   8192
#define STAGE_B 16384
#define NSTAGE  6

__global__ __launch_bounds__(256, 2) void main_mma(
    const float* __restrict__ bb, float* __restrict__ out)
{
    extern __shared__ char sm[];
    uint32_t sb = smem_u32(sm);
    const int tid = threadIdx.x, wid = tid >> 5, lane = tid & 31;
    const int n0 = blockIdx.x * 128, t0 = blockIdx.y * 128;
    const int warp_m = (wid & 3) * 32, warp_n = (wid >> 2) * 64;
    const int lrow = tid >> 2, lc = tid & 3;

    uint32_t aoffs[2][2], boffs[2][4];
#pragma unroll
    for (int kk = 0; kk < 2; kk++) {
#pragma unroll
        for (int mi = 0; mi < 2; mi++)
            aoffs[kk][mi] = sw_off(warp_m + mi * 16 + (lane & 15), kk * 2 + (lane >> 4));
#pragma unroll
        for (int p = 0; p < 4; p++)
            boffs[kk][p] = ST_WH + sw_off(warp_n + p * 16 + (lane & 7) + ((lane >> 4) << 3),
                                          kk * 2 + ((lane >> 3) & 1));
    }

    float acc[2][8][4];
#pragma unroll
    for (int a = 0; a < 2; a++)
#pragma unroll
        for (int b = 0; b < 8; b++)
#pragma unroll
            for (int c = 0; c < 4; c++) acc[a][b][c] = 0.f;

#define MN_ISSUE(s, k0) do {                                                  \
    uint32_t st = sb + (uint32_t)(s) * STAGE_B;                               \
    _Pragma("unroll")                                                         \
    for (int i = 0; i < 2; i++) {                                             \
        int row = lrow + i * 64;                                              \
        uint32_t so = sw_off(row, lc);                                        \
        CP_ASYNC16(st + so, g_xh + (size_t)(t0 + row) * DIM + (k0) + lc * 8); \
        CP_ASYNC16(st + ST_WH + so, g_wh + (size_t)(n0 + row) * DIM + (k0) + lc * 8); \
    }                                                                         \
    CP_COMMIT();                                                              \
} while (0)

#define MN_CHUNK(base_) do {                                                  \
    uint32_t base = (base_);                                                  \
    _Pragma("unroll")                                                         \
    for (int kk = 0; kk < 2; kk++) {                                          \
        uint32_t ah[2][4];                                                    \
        ldsm4(ah[0], base + aoffs[kk][0]);                                    \
        ldsm4(ah[1], base + aoffs[kk][1]);                                    \
        _Pragma("unroll")                                                     \
        for (int p = 0; p < 4; p++) {                                         \
            uint32_t bh[4];                                                   \
            ldsm4(bh, base + boffs[kk][p]);                                   \
            _Pragma("unroll")                                                 \
            for (int mi = 0; mi < 2; mi++) {                                  \
                mma16816(acc[mi][p * 2],     ah[mi], bh);                     \
                mma16816(acc[mi][p * 2 + 1], ah[mi], bh + 2);                 \
            }                                                                 \
        }                                                                     \
    }                                                                         \
} while (0)

    MN_ISSUE(0, 0);
    MN_ISSUE(1, 32);
    MN_ISSUE(2, 64);
    MN_ISSUE(3, 96);
    int rs = 0, is = 4;
    for (int p2 = 0; p2 < 32; p2++) {
        if (p2 < 31) { CP_WAIT(2); } else { CP_WAIT(0); }
        __syncthreads();
        int cnext = p2 * 2 + 4;
        if (cnext < 64) {
            MN_ISSUE(is, cnext * 32);
            if (++is == NSTAGE) is = 0;
            MN_ISSUE(is, (cnext + 1) * 32);
            if (++is == NSTAGE) is = 0;
        }
        MN_CHUNK(sb + (uint32_t)rs * STAGE_B);
        if (++rs == NSTAGE) rs = 0;
        MN_CHUNK(sb + (uint32_t)rs * STAGE_B);
        if (++rs == NSTAGE) rs = 0;
    }

    __syncthreads();

#pragma unroll
    for (int c2 = 0; c2 < 4; c2++) {
        uint32_t st = sb + (uint32_t)c2 * STAGE_B;
        int k0 = c2 * 32;
#pragma unroll
        for (int i = 0; i < 2; i++) {
            int row = lrow + i * 64;
            uint32_t so = sw_off(row, lc);
            CP_ASYNC16(st + so, g_hm + (size_t)(t0 + row) * ER + k0 + lc * 8);
            CP_ASYNC16(st + ST_WH + so, g_lBt + (size_t)(n0 + row) * ER + k0 + lc * 8);
        }
        CP_COMMIT();
    }

    float bias[8][2];
#pragma unroll
    for (int nt = 0; nt < 8; nt++) {
        int col = nt * 8 + (lane & 3) * 2;
        bias[nt][0] = __ldg(bb + n0 + warp_n + col);
        bias[nt][1] = __ldg(bb + n0 + warp_n + col + 1);
    }
#pragma unroll
    for (int mi = 0; mi < 2; mi++) {
#pragma unroll
        for (int h = 0; h < 2; h++) {
            int t = t0 + warp_m + mi * 16 + (lane >> 2) + h * 8;
            float* orow = out + (size_t)t * DIM + n0 + warp_n;
#pragma unroll
            for (int nt = 0; nt < 8; nt++) {
                int col = nt * 8 + (lane & 3) * 2;
                float2 v;
                v.x = gelu_exact(acc[mi][nt][h * 2] + bias[nt][0]);
                v.y = gelu_exact(acc[mi][nt][h * 2 + 1] + bias[nt][1]);
                *(float2*)(orow + col) = v;
            }
        }
    }

#pragma unroll
    for (int a = 0; a < 2; a++)
#pragma unroll
        for (int b = 0; b < 8; b++)
#pragma unroll
            for (int c = 0; c < 4; c++) acc[a][b][c] = 0.f;

    CP_WAIT(0);
    __syncthreads();
#pragma unroll
    for (int c2 = 0; c2 < 4; c2++)
        MN_CHUNK(sb + (uint32_t)c2 * STAGE_B);

#pragma unroll
    for (int mi = 0; mi < 2; mi++) {
#pragma unroll
        for (int h = 0; h < 2; h++) {
            int t = t0 + warp_m + mi * 16 + (lane >> 2) + h * 8;
            float* orow = out + (size_t)t * DIM + n0 + warp_n;
#pragma unroll
            for (int nt = 0; nt < 8; nt++) {
                int col = nt * 8 + (lane & 3) * 2;
                float2 v = *(float2*)(orow + col);
                v.x += acc[mi][nt][h * 2];
                v.y += acc[mi][nt][h * 2 + 1];
                *(float2*)(orow + col) = v;
            }
        }
    }
}

// ---------------------------------------------------------------------------
extern "C" void kernel_launch(void* const* d_in, const int* in_sizes, int n_in,
                              void* d_out, int out_size)
{
    const float* x  = (const float*)d_in[0];
    const float* gw = (const float*)d_in[1];
    const float* gb = (const float*)d_in[2];
    const float* bw = (const float*)d_in[3];
    const float* bb = (const float*)d_in[4];
    const float* lA = (const float*)d_in[5];
    const float* lB = (const float*)d_in[6];

    float* out   = (float*)d_out;
    float* probs = out + (size_t)T_TOK * (size_t)DIM;

    cudaFuncSetAttribute(main_mma, cudaFuncAttributeMaxDynamicSharedMemorySize, NSTAGE * STAGE_B);
    cudaFuncSetAttribute(loraA_fused, cudaFuncAttributeMaxDynamicSharedMemorySize, 4 * LA_STAGE);

    // prep: [0,512) router (2 tok/warp), [512,1536) pack_lA
    prep_fused<<<1536, 256>>>(x, gw, gb, probs, lA);
    // loraA + filler: [0,128) loraA, [128,2176) conv_w, [2176,3200) pack_lB
    loraA_fused<<<3200, 256, 4 * LA_STAGE>>>(bw, lB);
    main_mma<<<dim3(DIM / 128, T_TOK / 128), 256, NSTAGE * STAGE_B>>>(bb, out);
}

// round 17
// speedup vs baseline: 1.0103x; 1.0103x over previous
#include <cuda_runtime.h>
#include <cuda_fp16.h>
#include <math.h>
#include <stdint.h>

#define T_TOK 8192
#define DIM   2048
#define NE    8
#define RK    16
#define ER    128

// ---------------- device scratch ----------------
__device__ int   g_idx[T_TOK];
__device__ float g_w[T_TOK];
__device__ __align__(256) __half g_xh[T_TOK * DIM];
__device__ __align__(256) __half g_wh[DIM * DIM];
__device__ __align__(256) __half g_lAt[ER * DIM];   // [n=e*16+r][k]
__device__ __align__(256) __half g_lBt[DIM * ER];   // [n][k2]
__device__ __align__(256) __half g_hm[T_TOK * ER];  // masked scaled h

__device__ __forceinline__ float gelu_exact(float v) {
    return 0.5f * v * (1.0f + erff(v * 0.7071067811865476f));
}
__device__ __forceinline__ uint32_t smem_u32(const void* p) {
    uint32_t a;
    asm("{ .reg .u64 t; cvta.to.shared.u64 t, %1; cvt.u32.u64 %0, t; }" : "=r"(a) : "l"(p));
    return a;
}
#define CP_ASYNC16(dst, src) asm volatile("cp.async.cg.shared.global [%0], [%1], 16;" :: "r"(dst), "l"(src))
#define CP_COMMIT()          asm volatile("cp.async.commit_group;" ::: "memory")
#define CP_WAIT(n)           asm volatile("cp.async.wait_group %0;" :: "n"(n) : "memory")

__device__ __forceinline__ void ldsm4(uint32_t* r, uint32_t addr) {
    asm volatile("ldmatrix.sync.aligned.m8n8.x4.shared.b16 {%0,%1,%2,%3}, [%4];"
        : "=r"(r[0]), "=r"(r[1]), "=r"(r[2]), "=r"(r[3]) : "r"(addr));
}
__device__ __forceinline__ void mma16816(float* d, const uint32_t* a, const uint32_t* b) {
    asm volatile("mma.sync.aligned.m16n8k16.row.col.f32.f16.f16.f32 "
        "{%0,%1,%2,%3}, {%4,%5,%6,%7}, {%8,%9}, {%0,%1,%2,%3};"
        : "+f"(d[0]), "+f"(d[1]), "+f"(d[2]), "+f"(d[3])
        : "r"(a[0]), "r"(a[1]), "r"(a[2]), "r"(a[3]), "r"(b[0]), "r"(b[1]));
}
// smem tile: rows x 64B (32 halves), swizzled
__device__ __forceinline__ uint32_t sw_off(int row, int chunk) {
    return (uint32_t)(row * 64 + ((chunk ^ ((row >> 1) & 3)) << 4));
}

// ---------------- prep: router (2 tok/warp) + conv_w + pack_lA + pack_lB ----------------
__global__ __launch_bounds__(256) void prep_fused(
    const float* __restrict__ x, const float* __restrict__ gw,
    const float* __restrict__ gb, float* __restrict__ probs,
    const float* __restrict__ bw, const float* __restrict__ lA,
    const float* __restrict__ lB)
{
    const int b = blockIdx.x;
    if (b < 512) {
        // 16 tokens/block, 2 tokens/warp
        const int warp = threadIdx.x >> 5, lane = threadIdx.x & 31;
        const int tbase = b * 16 + warp * 2;

        float acc[2][NE];
#pragma unroll
        for (int tt = 0; tt < 2; tt++)
#pragma unroll
            for (int e = 0; e < NE; e++) acc[tt][e] = 0.f;

#pragma unroll 1
        for (int i = 0; i < 16; i++) {
            int k = lane * 4 + i * 128;
            float4 v[2];
#pragma unroll
            for (int tt = 0; tt < 2; tt++) {
                v[tt] = *(const float4*)(x + (size_t)(tbase + tt) * DIM + k);
                __half h[4] = {__float2half_rn(v[tt].x), __float2half_rn(v[tt].y),
                               __float2half_rn(v[tt].z), __float2half_rn(v[tt].w)};
                *(uint2*)(g_xh + (size_t)(tbase + tt) * DIM + k) = *(uint2*)h;
            }
#pragma unroll
            for (int e = 0; e < NE; e++) {
                float4 g = __ldg((const float4*)(gw + e * DIM + k));
#pragma unroll
                for (int tt = 0; tt < 2; tt++)
                    acc[tt][e] += v[tt].x * g.x + v[tt].y * g.y
                                + v[tt].z * g.z + v[tt].w * g.w;
            }
        }
#pragma unroll
        for (int tt = 0; tt < 2; tt++) {
#pragma unroll
            for (int e = 0; e < NE; e++)
#pragma unroll
                for (int o = 16; o > 0; o >>= 1)
                    acc[tt][e] += __shfl_xor_sync(0xffffffffu, acc[tt][e], o);
            if (lane == 0) {
                int t = tbase + tt;
                float m = -1e30f;
#pragma unroll
                for (int e = 0; e < NE; e++) { acc[tt][e] += gb[e]; m = fmaxf(m, acc[tt][e]); }
                float p[NE], s = 0.f;
#pragma unroll
                for (int e = 0; e < NE; e++) { p[e] = __expf(acc[tt][e] - m); s += p[e]; }
                float inv = 1.f / s;
                int best = 0; float bp = -1.f;
#pragma unroll
                for (int e = 0; e < NE; e++) {
                    p[e] *= inv;
                    probs[t * NE + e] = p[e];
                    if (p[e] > bp) { bp = p[e]; best = e; }
                }
                g_idx[t] = best; g_w[t] = bp;
            }
        }
    } else if (b < 2560) {
        // conv_w: 2 float4 per thread
        int i0 = (b - 512) * 512 + threadIdx.x;
#pragma unroll
        for (int r = 0; r < 2; r++) {
            int i = i0 + r * 256;
            float4 v = ((const float4*)bw)[i];
            __half h[4] = {__float2half_rn(v.x), __float2half_rn(v.y),
                           __float2half_rn(v.z), __float2half_rn(v.w)};
            ((uint2*)g_wh)[i] = *(uint2*)h;
        }
    } else if (b < 3584) {
        int idx = (b - 2560) * 256 + threadIdx.x;
        int k = idx & (DIM - 1), n = idx >> 11;
        g_lAt[idx] = __float2half_rn(lA[(size_t)((n >> 4) * DIM + k) * RK + (n & 15)]);
    } else {
        int idx = (b - 3584) * 256 + threadIdx.x;
        int k2 = idx & 127, n = idx >> 7;
        g_lBt[idx] = __float2half_rn(lB[(size_t)((k2 >> 4) * RK + (k2 & 15)) * DIM + n]);
    }
}

// ---------------- LoRA-A: BM=64, grid=128 ----------------
#define LA_STAGE 12288
#define LA_WOFF  4096
__global__ __launch_bounds__(256, 2) void loraA_mma() {
    extern __shared__ char sm[];
    uint32_t sb = smem_u32(sm);
    const int tid = threadIdx.x, wid = tid >> 5, lane = tid & 31;
    const int t0 = blockIdx.x * 64;
    const int warp_m = (wid & 1) * 32, warp_n = (wid >> 1) * 32;

    float acc[2][4][4];
#pragma unroll
    for (int a = 0; a < 2; a++)
#pragma unroll
        for (int b = 0; b < 4; b++)
#pragma unroll
            for (int c = 0; c < 4; c++) acc[a][b][c] = 0.f;

#define LA_ISSUE(s, k0) do {                                                  \
    uint32_t st = sb + (uint32_t)(s) * LA_STAGE;                              \
    { int row = tid >> 2, ch = tid & 3;                                       \
      CP_ASYNC16(st + sw_off(row, ch), g_xh + (size_t)(t0 + row) * DIM + (k0) + ch * 8); } \
    _Pragma("unroll")                                                         \
    for (int i = 0; i < 2; i++) {                                             \
        int idx = tid + i * 256;                                              \
        int row = idx >> 2, ch = idx & 3;                                     \
        CP_ASYNC16(st + LA_WOFF + sw_off(row, ch), g_lAt + (size_t)row * DIM + (k0) + ch * 8); \
    }                                                                         \
    CP_COMMIT();                                                              \
} while (0)

    LA_ISSUE(0, 0);
    LA_ISSUE(1, 32);
    LA_ISSUE(2, 64);
    for (int c = 0; c < 64; c++) {
        if (c < 62) { CP_WAIT(2); } else if (c == 62) { CP_WAIT(1); } else { CP_WAIT(0); }
        __syncthreads();
        if (c + 3 < 64) LA_ISSUE((c + 3) & 3, (c + 3) * 32);
        uint32_t base = sb + (uint32_t)(c & 3) * LA_STAGE;
#pragma unroll
        for (int kk = 0; kk < 2; kk++) {
            uint32_t ah[2][4];
#pragma unroll
            for (int mi = 0; mi < 2; mi++) {
                int r = warp_m + mi * 16 + (lane & 15);
                ldsm4(ah[mi], base + sw_off(r, kk * 2 + (lane >> 4)));
            }
#pragma unroll
            for (int p = 0; p < 2; p++) {
                uint32_t bh[4];
                int r = warp_n + p * 16 + (lane & 7) + ((lane >> 4) << 3);
                ldsm4(bh, base + LA_WOFF + sw_off(r, kk * 2 + ((lane >> 3) & 1)));
#pragma unroll
                for (int mi = 0; mi < 2; mi++) {
                    mma16816(acc[mi][p * 2], ah[mi], bh);
                    mma16816(acc[mi][p * 2 + 1], ah[mi], bh + 2);
                }
            }
        }
    }
#pragma unroll
    for (int mi = 0; mi < 2; mi++) {
#pragma unroll
        for (int h = 0; h < 2; h++) {
            int t = t0 + warp_m + mi * 16 + (lane >> 2) + h * 8;
            int se = g_idx[t];
            float wv = g_w[t];
#pragma unroll
            for (int nt = 0; nt < 4; nt++) {
                int col = warp_n + nt * 8 + (lane & 3) * 2;
                float v0 = ((col >> 4) == se) ? wv * gelu_exact(acc[mi][nt][h * 2]) : 0.f;
                float v1 = (((col + 1) >> 4) == se) ? wv * gelu_exact(acc[mi][nt][h * 2 + 1]) : 0.f;
                __half2 p2 = __floats2half2_rn(v0, v1);
                *(uint32_t*)(g_hm + (size_t)t * ER + col) = *(uint32_t*)&p2;
            }
        }
    }
}

// ---------------- main kernel: BM=BN=128, BK=32, 6 stages, paired chunks ----------------
#define ST_WH   8192
#define STAGE_B 16384
#define NSTAGE  6

__global__ __launch_bounds__(256, 2) void main_mma(
    const float* __restrict__ bb, float* __restrict__ out)
{
    extern __shared__ char sm[];
    uint32_t sb = smem_u32(sm);
    const int tid = threadIdx.x, wid = tid >> 5, lane = tid & 31;
    const int n0 = blockIdx.x * 128, t0 = blockIdx.y * 128;
    const int warp_m = (wid & 3) * 32, warp_n = (wid >> 2) * 64;
    const int lrow = tid >> 2, lc = tid & 3;

    uint32_t aoffs[2][2], boffs[2][4];
#pragma unroll
    for (int kk = 0; kk < 2; kk++) {
#pragma unroll
        for (int mi = 0; mi < 2; mi++)
            aoffs[kk][mi] = sw_off(warp_m + mi * 16 + (lane & 15), kk * 2 + (lane >> 4));
#pragma unroll
        for (int p = 0; p < 4; p++)
            boffs[kk][p] = ST_WH + sw_off(warp_n + p * 16 + (lane & 7) + ((lane >> 4) << 3),
                                          kk * 2 + ((lane >> 3) & 1));
    }

    float acc[2][8][4];
#pragma unroll
    for (int a = 0; a < 2; a++)
#pragma unroll
        for (int b = 0; b < 8; b++)
#pragma unroll
            for (int c = 0; c < 4; c++) acc[a][b][c] = 0.f;

#define MN_ISSUE(s, k0) do {                                                  \
    uint32_t st = sb + (uint32_t)(s) * STAGE_B;                               \
    _Pragma("unroll")                                                         \
    for (int i = 0; i < 2; i++) {                                             \
        int row = lrow + i * 64;                                              \
        uint32_t so = sw_off(row, lc);                                        \
        CP_ASYNC16(st + so, g_xh + (size_t)(t0 + row) * DIM + (k0) + lc * 8); \
        CP_ASYNC16(st + ST_WH + so, g_wh + (size_t)(n0 + row) * DIM + (k0) + lc * 8); \
    }                                                                         \
    CP_COMMIT();                                                              \
} while (0)

#define MN_CHUNK(base_) do {                                                  \
    uint32_t base = (base_);                                                  \
    _Pragma("unroll")                                                         \
    for (int kk = 0; kk < 2; kk++) {                                          \
        uint32_t ah[2][4];                                                    \
        ldsm4(ah[0], base + aoffs[kk][0]);                                    \
        ldsm4(ah[1], base + aoffs[kk][1]);                                    \
        _Pragma("unroll")                                                     \
        for (int p = 0; p < 4; p++) {                                         \
            uint32_t bh[4];                                                   \
            ldsm4(bh, base + boffs[kk][p]);                                   \
            _Pragma("unroll")                                                 \
            for (int mi = 0; mi < 2; mi++) {                                  \
                mma16816(acc[mi][p * 2],     ah[mi], bh);                     \
                mma16816(acc[mi][p * 2 + 1], ah[mi], bh + 2);                 \
            }                                                                 \
        }                                                                     \
    }                                                                         \
} while (0)

    MN_ISSUE(0, 0);
    MN_ISSUE(1, 32);
    MN_ISSUE(2, 64);
    MN_ISSUE(3, 96);
    int rs = 0, is = 4;
    for (int p2 = 0; p2 < 32; p2++) {
        if (p2 < 31) { CP_WAIT(2); } else { CP_WAIT(0); }
        __syncthreads();
        int cnext = p2 * 2 + 4;
        if (cnext < 64) {
            MN_ISSUE(is, cnext * 32);
            if (++is == NSTAGE) is = 0;
            MN_ISSUE(is, (cnext + 1) * 32);
            if (++is == NSTAGE) is = 0;
        }
        MN_CHUNK(sb + (uint32_t)rs * STAGE_B);
        if (++rs == NSTAGE) rs = 0;
        MN_CHUNK(sb + (uint32_t)rs * STAGE_B);
        if (++rs == NSTAGE) rs = 0;
    }

    __syncthreads();

#pragma unroll
    for (int c2 = 0; c2 < 4; c2++) {
        uint32_t st = sb + (uint32_t)c2 * STAGE_B;
        int k0 = c2 * 32;
#pragma unroll
        for (int i = 0; i < 2; i++) {
            int row = lrow + i * 64;
            uint32_t so = sw_off(row, lc);
            CP_ASYNC16(st + so, g_hm + (size_t)(t0 + row) * ER + k0 + lc * 8);
            CP_ASYNC16(st + ST_WH + so, g_lBt + (size_t)(n0 + row) * ER + k0 + lc * 8);
        }
        CP_COMMIT();
    }

    float bias[8][2];
#pragma unroll
    for (int nt = 0; nt < 8; nt++) {
        int col = nt * 8 + (lane & 3) * 2;
        bias[nt][0] = __ldg(bb + n0 + warp_n + col);
        bias[nt][1] = __ldg(bb + n0 + warp_n + col + 1);
    }
#pragma unroll
    for (int mi = 0; mi < 2; mi++) {
#pragma unroll
        for (int h = 0; h < 2; h++) {
            int t = t0 + warp_m + mi * 16 + (lane >> 2) + h * 8;
            float* orow = out + (size_t)t * DIM + n0 + warp_n;
#pragma unroll
            for (int nt = 0; nt < 8; nt++) {
                int col = nt * 8 + (lane & 3) * 2;
                float2 v;
                v.x = gelu_exact(acc[mi][nt][h * 2] + bias[nt][0]);
                v.y = gelu_exact(acc[mi][nt][h * 2 + 1] + bias[nt][1]);
                *(float2*)(orow + col) = v;
            }
        }
    }

#pragma unroll
    for (int a = 0; a < 2; a++)
#pragma unroll
        for (int b = 0; b < 8; b++)
#pragma unroll
            for (int c = 0; c < 4; c++) acc[a][b][c] = 0.f;

    CP_WAIT(0);
    __syncthreads();
#pragma unroll
    for (int c2 = 0; c2 < 4; c2++)
        MN_CHUNK(sb + (uint32_t)c2 * STAGE_B);

#pragma unroll
    for (int mi = 0; mi < 2; mi++) {
#pragma unroll
        for (int h = 0; h < 2; h++) {
            int t = t0 + warp_m + mi * 16 + (lane >> 2) + h * 8;
            float* orow = out + (size_t)t * DIM + n0 + warp_n;
#pragma unroll
            for (int nt = 0; nt < 8; nt++) {
                int col = nt * 8 + (lane & 3) * 2;
                float2 v = *(float2*)(orow + col);
                v.x += acc[mi][nt][h * 2];
                v.y += acc[mi][nt][h * 2 + 1];
                *(float2*)(orow + col) = v;
            }
        }
    }
}

// ---------------------------------------------------------------------------
extern "C" void kernel_launch(void* const* d_in, const int* in_sizes, int n_in,
                              void* d_out, int out_size)
{
    const float* x  = (const float*)d_in[0];
    const float* gw = (const float*)d_in[1];
    const float* gb = (const float*)d_in[2];
    const float* bw = (const float*)d_in[3];
    const float* bb = (const float*)d_in[4];
    const float* lA = (const float*)d_in[5];
    const float* lB = (const float*)d_in[6];

    float* out   = (float*)d_out;
    float* probs = out + (size_t)T_TOK * (size_t)DIM;

    cudaFuncSetAttribute(main_mma, cudaFuncAttributeMaxDynamicSharedMemorySize, NSTAGE * STAGE_B);
    cudaFuncSetAttribute(loraA_mma, cudaFuncAttributeMaxDynamicSharedMemorySize, 4 * LA_STAGE);

    // prep: [0,512) router (2 tok/warp), [512,2560) conv_w x2, [2560,3584) pack_lA, [3584,4608) pack_lB
    prep_fused<<<4608, 256>>>(x, gw, gb, probs, bw, lA, lB);
    loraA_mma<<<T_TOK / 64, 256, 4 * LA_STAGE>>>();
    main_mma<<<dim3(DIM / 128, T_TOK / 128), 256, NSTAGE * STAGE_B>>>(bb, out);
}